// round 12
// baseline (speedup 1.0000x reference)
#include <cuda_runtime.h>
#include <cstdint>

// ---------------------------------------------------------------------------
// DSS kernel: out[l,h] = Re( sum_n Wk[h,n] * exp(dtLambda[h,n] * l) )
// Fastpath (H=1024, N=64, L=2048): SINGLE fused kernel.
//   One-wave topology: block = 64 thr = 2 warps = 2 h, one L-half.
//   grid = 1024 <= 8 blocks/SM x 148 capacity -> single wave (1.4% quant).
//   Each warp: full n-sum for its h, ILP-4 body (2 n-pairs per jj, 4
//   independent mul-fma chains + tree accumulate), NJJ=16.
// ---------------------------------------------------------------------------

#define EPS2 1e-14f   // EPS^2, EPS = 1e-7

#define FH 1024
#define FN 64
#define FL 2048
#define FNP 32          // n-pairs total (all owned by one warp)
#define HT  2           // h per block
#define NJJ 16          // recurrence steps (each covers 2 output phases)

#define INV_2PI 0.15915494309189535f
#define PI2_HI  6.2831854820251465f
#define PI2_LO  (-1.7484556000744483e-7f)
#define INV2PI_D 0.15915494309189535
#define TWOPI_D  6.283185307179586

typedef unsigned long long u64;
#define PK(d, lo, hi)   asm("mov.b64 %0, {%1, %2};" : "=l"(d) : "f"(lo), "f"(hi))
#define UPK(lo, hi, v)  asm("mov.b64 {%0, %1}, %2;" : "=f"(lo), "=f"(hi) : "l"(v))
#define MUL2(d, a, b)   asm("mul.rn.f32x2 %0, %1, %2;" : "=l"(d) : "l"(a), "l"(b))
#define ADD2(d, a, b)   asm("add.rn.f32x2 %0, %1, %2;" : "=l"(d) : "l"(a), "l"(b))
#define FMA2(d, a, b, c) asm("fma.rn.f32x2 %0, %1, %2, %3;" : "=l"(d) : "l"(a), "l"(b), "l"(c))

// fast sin/cos with explicit Cody-Waite reduction to [-pi, pi]
__device__ __forceinline__ void fast_sincos(float th, float* s, float* c)
{
    float k = rintf(th * INV_2PI);
    float r = fmaf(-k, PI2_HI, th);
    r = fmaf(-k, PI2_LO, r);
    *s = __sinf(r);
    *c = __cosf(r);
}

// precise: reduce mult*b in double, then sincosf on the small residue
__device__ __forceinline__ void dp_sincos(float b, float mult, float* s, float* c)
{
    double th = (double)mult * (double)b;
    double k = rint(th * INV2PI_D);
    float r = (float)(th - k * TWOPI_D);
    sincosf(r, s, c);
}

// ---------------------------------------------------------------------------
// Fused kernel. Block = (htile, half): 64 threads, 2 warps; warp = h0 + w.
// smem const slots per (h_local, np), each float4 (parity-packed pairs):
//   s0: (a0, a1, b0, b1)
//   s1: (wkr0, wkr1, nwki0, nwki1)    wk includes z^1024 rotation if half
//   s2: (wki0, wki1, m1r0, m1r1)      m1 = z^32
//   s3: (nm1i0, nm1i1, A1_0, A1_1)    A1 = 2 Re z^32
//   s4: (nB1_0, nB1_1, A2_0, A2_1)    B1 = e^{64a}, A2 = 2 Re z^64
//   s5: (nB2_0, nB2_1, 0, 0)          B2 = e^{128a}
// ---------------------------------------------------------------------------
struct ChainState { u64 cme, cmo, ce, co, A2, nB2; };

__global__ void __launch_bounds__(64, 8) k_fused(
    const float* __restrict__ log_dt,
    const float* __restrict__ llnr,
    const float* __restrict__ lim,
    const float* __restrict__ W,
    float* __restrict__ out)
{
    __shared__ float4 npcs[6][HT][FNP];
    __shared__ float tileA[32][33];
    __shared__ float tileB[32][33];

    const int blk   = blockIdx.x;         // htile*2 + half
    const int half  = blk & 1;
    const int htile = blk >> 1;
    const int h0    = htile * HT;
    const int tid   = threadIdx.x;
    const int hl    = tid >> 5;            // warp -> h_local
    const int p     = tid & 31;

    // ---------------- Phase 1: per-(h, np) constants (all 64 threads) --------
    {
        const int np = p;
        const int h  = h0 + hl;

        float dtr = expf(log_dt[2 * h + 0]);
        float dti = expf(log_dt[2 * h + 1]);

        float a_[2], b_[2], wkr_[2], wki_[2];
        float m1r_[2], nm1i_[2], A1_[2], nB1_[2], A2_[2], nB2_[2];

#pragma unroll
        for (int par = 0; par < 2; par++) {
            int n = 2 * np + par;
            float lr = -expf(llnr[n]);
            float li = lim[n];
            float a = dtr * lr;      // < 0
            float b = dti * li;
            a_[par] = a;  b_[par] = b;

            // Wk = Wc * (exp(dtL)-1) * reciprocal_clamped(Lambda)
            float ns = fmaxf(lr * lr + li * li, EPS2);
            float rr =  lr / ns;
            float ri = -li / ns;
            float ea = expf(a), sb, cb;
            sincosf(b, &sb, &cb);
            float edr = ea * cb - 1.0f;
            float edi = ea * sb;
            float wr = W[(h * FN + n) * 2 + 0];
            float wi = W[(h * FN + n) * 2 + 1];
            float tr = wr * edr - wi * edi;
            float ti = wr * edi + wi * edr;
            float wkr = tr * rr - ti * ri;
            float wki = tr * ri + ti * rr;

            if (half) {              // fold z^1024 rotation into Wk (precise)
                float s1k, c1k;
                dp_sincos(b, 1024.0f, &s1k, &c1k);
                float e1k = expf(1024.0f * a);
                float qr = e1k * c1k, qi = e1k * s1k;
                float nwr = wkr * qr - wki * qi;
                float nwi = wkr * qi + wki * qr;
                wkr = nwr;  wki = nwi;
            }
            wkr_[par] = wkr;  wki_[par] = wki;

            // m1 = z^32 (DP-reduced angle)
            float s32, c32;
            dp_sincos(b, 32.0f, &s32, &c32);
            float e32 = expf(32.0f * a);
            float m1r = e32 * c32, m1i = e32 * s32;
            m1r_[par]  = m1r;
            nm1i_[par] = -m1i;

            float e64 = e32 * e32;                // e^{64a}
            A1_[par]  = 2.0f * m1r;
            nB1_[par] = -e64;
            A2_[par]  = 2.0f * (m1r * m1r - m1i * m1i);
            nB2_[par] = -e64 * e64;               // -e^{128a}
        }

        npcs[0][hl][np] = make_float4(a_[0], a_[1], b_[0], b_[1]);
        npcs[1][hl][np] = make_float4(wkr_[0], wkr_[1], -wki_[0], -wki_[1]);
        npcs[2][hl][np] = make_float4(wki_[0], wki_[1], m1r_[0], m1r_[1]);
        npcs[3][hl][np] = make_float4(nm1i_[0], nm1i_[1], A1_[0], A1_[1]);
        npcs[4][hl][np] = make_float4(nB1_[0], nB1_[1], A2_[0], A2_[1]);
        npcs[5][hl][np] = make_float4(nB2_[0], nB2_[1], 0.0f, 0.0f);
    }
    __syncthreads();

    // ---------------- Phase 2: ILP-4 recurrence (2 pairs per jj) -------------
    const float lm = (float)p - 64.0f;   // seed G at l = half*1024 + p - 64

    u64 acc[2 * NJJ];
#pragma unroll
    for (int j = 0; j < 2 * NJJ; j++) acc[j] = 0ULL;

    auto seeds = [&](int np, ChainState& s) {
        float4 ab = npcs[0][hl][np];
        ulonglong2 s1 = *reinterpret_cast<const ulonglong2*>(&npcs[1][hl][np]);
        ulonglong2 s2 = *reinterpret_cast<const ulonglong2*>(&npcs[2][hl][np]);
        ulonglong2 s3 = *reinterpret_cast<const ulonglong2*>(&npcs[3][hl][np]);
        ulonglong2 s4 = *reinterpret_cast<const ulonglong2*>(&npcs[4][hl][np]);
        ulonglong2 s5 = *reinterpret_cast<const ulonglong2*>(&npcs[5][hl][np]);

        float e0 = __expf(ab.x * lm);
        float e1 = __expf(ab.y * lm);
        float s0f, c0f, s1f, c1f;
        fast_sincos(ab.z * lm, &s0f, &c0f);
        fast_sincos(ab.w * lm, &s1f, &c1f);
        u64 Er2, Ei2;
        PK(Er2, e0 * c0f, e1 * c1f);
        PK(Ei2, e0 * s0f, e1 * s1f);

        u64 Gr, Gi, t;
        MUL2(t, s1.x, Er2);  FMA2(Gr, s1.y, Ei2, t);    // wkr*Er - wki*Ei
        MUL2(t, s1.x, Ei2);  FMA2(Gi, s2.x, Er2, t);    // wkr*Ei + wki*Er

        s.cme = Gr;                                      // x(p-64)
        MUL2(t, s2.y, Gr);     FMA2(s.cmo, s3.x, Gi, t);    // x(p-32)
        MUL2(t, s3.y, s.cmo);  FMA2(s.ce,  s4.x, s.cme, t); // x(p)
        MUL2(t, s3.y, s.ce);   FMA2(s.co,  s4.x, s.cmo, t); // x(p+32)
        s.A2  = s4.y;
        s.nB2 = s5.x;
    };

    // dual-pair body: 4 independent chains + tree accumulate
    auto body2 = [&](ChainState a, ChainState b) {
#pragma unroll
        for (int jj = 0; jj < NJJ; jj++) {
            u64 se, so;
            ADD2(se, a.ce, b.ce);
            ADD2(so, a.co, b.co);
            ADD2(acc[2 * jj],     acc[2 * jj],     se);
            ADD2(acc[2 * jj + 1], acc[2 * jj + 1], so);
            u64 te1, to1, te2, to2;
            MUL2(te1, a.ce, a.A2);  FMA2(te1, a.cme, a.nB2, te1);
            MUL2(to1, a.co, a.A2);  FMA2(to1, a.cmo, a.nB2, to1);
            MUL2(te2, b.ce, b.A2);  FMA2(te2, b.cme, b.nB2, te2);
            MUL2(to2, b.co, b.A2);  FMA2(to2, b.cmo, b.nB2, to2);
            a.cme = a.ce;  a.ce = te1;
            a.cmo = a.co;  a.co = to1;
            b.cme = b.ce;  b.ce = te2;
            b.cmo = b.co;  b.co = to2;
        }
    };

#pragma unroll 1
    for (int g = 0; g < FNP / 2; g++) {
        ChainState sA, sB;
        seeds(2 * g,     sA);
        seeds(2 * g + 1, sB);
        body2(sA, sB);
    }

    // ---------------- Phase 3: transpose + coalesced stores ------------------
    {
        float (*tile)[33] = hl ? tileB : tileA;
#pragma unroll
        for (int j = 0; j < 2 * NJJ; j++) {
            float lo, hi;
            UPK(lo, hi, acc[j]);
            tile[j][p] = lo + hi;
        }
    }
    __syncthreads();

    {
        const int kk = tid >> 5;        // k parity (2 warps)
        const int pp = tid & 31;        // l phase within 32
        const int l0 = half << 10;
#pragma unroll
        for (int k = kk; k < 2 * NJJ; k += 2) {
            float2 v = make_float2(tileA[k][pp], tileB[k][pp]);
            *reinterpret_cast<float2*>(out + (size_t)(l0 + (k << 5) + pp) * FH + h0) = v;
        }
    }
}

// ---------------------------------------------------------------------------
// Generic fallback (correct for any shape; slow).
// ---------------------------------------------------------------------------
__global__ void k_generic(const float* __restrict__ log_dt,
                          const float* __restrict__ llnr,
                          const float* __restrict__ lim,
                          const float* __restrict__ W,
                          float* __restrict__ out,
                          int H, int N, int L)
{
    int idx = blockIdx.x * blockDim.x + threadIdx.x;
    if (idx >= L * H) return;
    int l = idx / H, h = idx - l * H;
    float dtr = expf(log_dt[2 * h + 0]);
    float dti = expf(log_dt[2 * h + 1]);
    float fl = (float)l;
    float sum = 0.0f;
    for (int n = 0; n < N; n++) {
        float lr = -expf(llnr[n]);
        float li = lim[n];
        float a = dtr * lr, b = dti * li;
        float ns = fmaxf(lr * lr + li * li, EPS2);
        float rr = lr / ns, ri = -li / ns;
        float ea = expf(a), sb, cb;
        sincosf(b, &sb, &cb);
        float edr = ea * cb - 1.0f, edi = ea * sb;
        float wr = W[(h * N + n) * 2 + 0], wi = W[(h * N + n) * 2 + 1];
        float tr = wr * edr - wi * edi, ti = wr * edi + wi * edr;
        float wkr = tr * rr - ti * ri, wki = tr * ri + ti * rr;
        float el = expf(a * fl), sl, cl;
        sincosf(b * fl, &sl, &cl);
        sum += wkr * (el * cl) - wki * (el * sl);
    }
    out[idx] = sum;
}

// ---------------------------------------------------------------------------
extern "C" void kernel_launch(void* const* d_in, const int* in_sizes, int n_in,
                              void* d_out, int out_size)
{
    const float* log_dt = (const float*)d_in[0];   // (H,2)
    const float* llnr   = (const float*)d_in[1];   // (N,)
    const float* lim    = (const float*)d_in[2];   // (N,)
    const float* W      = (const float*)d_in[3];   // (H,N,2)
    float* out = (float*)d_out;

    int H = in_sizes[0] / 2;
    int N = in_sizes[1];
    int L = out_size / H;

    if (H == FH && N == FN && L == FL) {
        k_fused<<<(FH / HT) * 2, HT * 32>>>(log_dt, llnr, lim, W, out);
    } else {
        int tot = L * H;
        k_generic<<<(tot + 255) / 256, 256>>>(log_dt, llnr, lim, W, out, H, N, L);
    }
}

// round 14
// speedup vs baseline: 1.2989x; 1.2989x over previous
#include <cuda_runtime.h>
#include <cuda_bf16.h>
#include <cstdint>

// ---------------------------------------------------------------------------
// DSS kernel via warp-level tensor cores (mma.sync bf16 — baseline sm_80+ PTX,
// compiles for sm_100 without the 'a' suffix that tcgen05 needs).
//
// out[l,h] = Re( sum_n Wk[h,n] * z_{h,n}^l ),  l = 16*j + dl.
//   A_h[j, k]  (M=128 x 128) : k=2n -> Re(Wk z^16j), k=2n+1 -> Im(Wk z^16j)
//   B_h[dl, k] (N=16  x 128) : k=2n -> Re(z^dl),     k=2n+1 -> -Im(z^dl)
//   D = A . B^T (fp32 accum) => out[16j+dl, h].
// bf16 hi/lo split: D = Ah.Bh + Al.Bh + Ah.Bl  (error ~ Al.Bl ~ 1.5e-5 rel).
// One CTA = 8 h (sequential), 256 threads; warp m owns M-tile m (16 j rows).
// ---------------------------------------------------------------------------

#define EPS2 1e-14f

#define FH 1024
#define FN 64
#define FL 2048

#define INV_2PI 0.15915494309189535f
#define PI2_HI  6.2831854820251465f
#define PI2_LO  (-1.7484556000744483e-7f)

// ---- smem layout (bytes). A/B rows padded to 264 bf16 = 528 B ----
#define APITCH     528
#define SMEM_A     0                       // 128 x 528 = 67584
#define SMEM_B     67584                   // 16 x 528  =  8448
#define SMEM_STAGE 76032                   // 2048 x 9 f32 = 73728
#define SMEM_CA    149760                  // float4[512] = 8192
#define SMEM_CG    157952                  // float2[512] = 4096
#define SMEM_TOTAL 162048

// ---- PTX helpers ----
__device__ __forceinline__ uint32_t smem_u32(const void* p) {
    uint32_t a;
    asm("{ .reg .u64 t; cvta.to.shared.u64 t, %1; cvt.u32.u64 %0, t; }"
        : "=r"(a) : "l"(p));
    return a;
}

#define LDMATRIX_X4(r0, r1, r2, r3, addr)                                    \
    asm volatile("ldmatrix.sync.aligned.m8n8.x4.shared.b16 {%0,%1,%2,%3}, [%4];" \
        : "=r"(r0), "=r"(r1), "=r"(r2), "=r"(r3) : "r"(addr))

#define MMA_BF16(d, a0, a1, a2, a3, b0, b1)                                  \
    asm volatile("mma.sync.aligned.m16n8k16.row.col.f32.bf16.bf16.f32 "      \
        "{%0,%1,%2,%3}, {%4,%5,%6,%7}, {%8,%9}, {%0,%1,%2,%3};"              \
        : "+f"((d)[0]), "+f"((d)[1]), "+f"((d)[2]), "+f"((d)[3])             \
        : "r"(a0), "r"(a1), "r"(a2), "r"(a3), "r"(b0), "r"(b1))

// packs r = {hi: bf16(y), lo: bf16(x)}  (memory order: x then y)
#define CVT2(r, x, y) asm("cvt.rn.satfinite.bf16x2.f32 %0, %1, %2;" : "=r"(r) : "f"(y), "f"(x))

// fast sin/cos with Cody-Waite reduction to [-pi, pi] (float, FMA-exact)
__device__ __forceinline__ void fast_sincos(float th, float* s, float* c)
{
    float k = rintf(th * INV_2PI);
    float r = fmaf(-k, PI2_HI, th);
    r = fmaf(-k, PI2_LO, r);
    *s = __sinf(r);
    *c = __cosf(r);
}
// same reduction, precise sincosf on the small residue (for constants)
__device__ __forceinline__ void cw_sincos(float th, float* s, float* c)
{
    float k = rintf(th * INV_2PI);
    float r = fmaf(-k, PI2_HI, th);
    r = fmaf(-k, PI2_LO, r);
    sincosf(r, s, c);
}

// ---------------------------------------------------------------------------
__global__ void __launch_bounds__(256, 1) k_tc(
    const float* __restrict__ log_dt,
    const float* __restrict__ llnr,
    const float* __restrict__ lim,
    const float* __restrict__ W,
    float* __restrict__ out)
{
    extern __shared__ char smem[];
    const uint32_t sb = smem_u32(smem);
    const int tid  = threadIdx.x;
    const int wid  = tid >> 5;
    const int lane = tid & 31;
    const int h0   = blockIdx.x * 8;

    float4* cA = (float4*)(smem + SMEM_CA);   // (a, b, m16r, m16i)
    float2* cG = (float2*)(smem + SMEM_CG);   // (Wk_re, Wk_im)
    float*  stage = (float*)(smem + SMEM_STAGE);

    // ---- P1: per-(hh, n) constants ------------------------------------------
    for (int idx = tid; idx < 512; idx += 256) {
        int hh = idx >> 6, n = idx & 63;
        int h = h0 + hh;

        float lr = -expf(llnr[n]);
        float li = lim[n];
        float dtr = expf(log_dt[2 * h + 0]);
        float dti = expf(log_dt[2 * h + 1]);
        float a = dtr * lr;        // < 0
        float b = dti * li;

        // Wk = Wc * (exp(dtL)-1) * reciprocal_clamped(Lambda)
        float ns = fmaxf(lr * lr + li * li, EPS2);
        float rr =  lr / ns;
        float ri = -li / ns;
        float ea = expf(a), sbf, cbf;
        sincosf(b, &sbf, &cbf);
        float edr = ea * cbf - 1.0f;
        float edi = ea * sbf;
        float wr = W[(h * FN + n) * 2 + 0];
        float wi = W[(h * FN + n) * 2 + 1];
        float tr = wr * edr - wi * edi;
        float ti = wr * edi + wi * edr;
        float gr = tr * rr - ti * ri;
        float gi = tr * ri + ti * rr;

        // m16 = z^16 (CW-reduced angle, precise sincos)
        float s16, c16;
        cw_sincos(16.0f * b, &s16, &c16);
        float e16 = expf(16.0f * a);

        cA[idx] = make_float4(a, b, e16 * c16, e16 * s16);
        cG[idx] = make_float2(gr, gi);
    }
    __syncthreads();

    // per-warp ldmatrix base addresses (lane-dependent parts)
    const uint32_t a_lanebase = sb + SMEM_A
        + (uint32_t)(16 * wid + (lane & 15)) * APITCH + ((lane >> 4) << 4);
    const uint32_t b_lanebase = sb + SMEM_B
        + (uint32_t)(((lane >> 4) & 1) * 8 + (lane & 7)) * APITCH
        + (((lane >> 3) & 1) << 4);

    const int n_ = tid & 63;
    const int q_ = tid >> 6;     // j-quarter 0..3

    for (int hh = 0; hh < 8; hh++) {
        // ---- build A: S_j = Wk * z^(16 j); thread does j = 32 q_ .. +31 ------
        {
            float4 ab = cA[hh * 64 + n_];
            float2 G  = cG[hh * 64 + n_];
            float Sr = G.x, Si = G.y;
            if (q_) {            // rotate by z^(512 q_)
                float mult = 512.0f * (float)q_;
                float s, c;
                fast_sincos(ab.y * mult, &s, &c);
                float e = __expf(ab.x * mult);
                float zr = e * c, zi = e * s;
                float t = Sr * zr - Si * zi;
                Si = Sr * zi + Si * zr;
                Sr = t;
            }
            const float mr = ab.z, mi = ab.w;
            uint32_t wbase = sb + SMEM_A + (uint32_t)(q_ * 32) * APITCH + 4u * n_;
#pragma unroll 8
            for (int s = 0; s < 32; s++) {
                uint32_t rh;
                CVT2(rh, Sr, Si);
                float frh = __uint_as_float(rh << 16);
                float fih = __uint_as_float(rh & 0xFFFF0000u);
                uint32_t rl;
                CVT2(rl, Sr - frh, Si - fih);
                asm volatile("st.shared.b32 [%0], %1;" :: "r"(wbase), "r"(rh) : "memory");
                asm volatile("st.shared.b32 [%0], %1;" :: "r"(wbase + 256u), "r"(rl) : "memory");
                wbase += APITCH;
                float t = Sr * mr - Si * mi;
                Si = Sr * mi + Si * mr;
                Sr = t;
            }
        }
        // ---- build B: (Re z^dl, -Im z^dl); threads 0..63, one n each ---------
        if (tid < 64) {
            float4 ab = cA[hh * 64 + tid];
            float e = __expf(ab.x);
            float s, c;
            fast_sincos(ab.y, &s, &c);
            float zr = e * c, zi = e * s;
            float Er = 1.0f, Ei = 0.0f;
            uint32_t wbase = sb + SMEM_B + 4u * tid;
#pragma unroll
            for (int dl = 0; dl < 16; dl++) {
                float vr = Er, vi = -Ei;
                uint32_t rh;
                CVT2(rh, vr, vi);
                float frh = __uint_as_float(rh << 16);
                float fih = __uint_as_float(rh & 0xFFFF0000u);
                uint32_t rl;
                CVT2(rl, vr - frh, vi - fih);
                asm volatile("st.shared.b32 [%0], %1;" :: "r"(wbase), "r"(rh) : "memory");
                asm volatile("st.shared.b32 [%0], %1;" :: "r"(wbase + 256u), "r"(rl) : "memory");
                wbase += APITCH;
                float t = Er * zr - Ei * zi;
                Ei = Er * zi + Ei * zr;
                Er = t;
            }
        }
        __syncthreads();

        // ---- MMA: warp wid = M-tile; 3 passes x 8 k-chunks x 2 N-tiles -------
        float d0[4] = {0.f, 0.f, 0.f, 0.f};
        float d1[4] = {0.f, 0.f, 0.f, 0.f};
#pragma unroll
        for (int pass = 0; pass < 3; pass++) {
            const uint32_t haB = (pass == 1) ? 256u : 0u;   // A lo half
            const uint32_t hbB = (pass == 2) ? 256u : 0u;   // B lo half
#pragma unroll
            for (int c = 0; c < 8; c++) {
                uint32_t a0, a1, a2, a3, b0, b1, b2, b3;
                LDMATRIX_X4(a0, a1, a2, a3, a_lanebase + haB + 32u * c);
                LDMATRIX_X4(b0, b1, b2, b3, b_lanebase + hbB + 32u * c);
                MMA_BF16(d0, a0, a1, a2, a3, b0, b1);   // N-tile 0 (dl 0..7)
                MMA_BF16(d1, a0, a1, a2, a3, b2, b3);   // N-tile 1 (dl 8..15)
            }
        }

        // ---- write D to stage[(j*16+dl)*9 + hh] ------------------------------
        {
            const int g  = lane >> 2;
            const int tc = lane & 3;
            const int j0 = 16 * wid + g;
            const int j1 = j0 + 8;
            const int dA = 2 * tc;       // tile0 dl
            const int dB = 8 + 2 * tc;   // tile1 dl
            stage[(j0 * 16 + dA)     * 9 + hh] = d0[0];
            stage[(j0 * 16 + dA + 1) * 9 + hh] = d0[1];
            stage[(j1 * 16 + dA)     * 9 + hh] = d0[2];
            stage[(j1 * 16 + dA + 1) * 9 + hh] = d0[3];
            stage[(j0 * 16 + dB)     * 9 + hh] = d1[0];
            stage[(j0 * 16 + dB + 1) * 9 + hh] = d1[1];
            stage[(j1 * 16 + dB)     * 9 + hh] = d1[2];
            stage[(j1 * 16 + dB + 1) * 9 + hh] = d1[3];
        }
        __syncthreads();   // all reads of A/B done before next-h rebuild
    }

    // ---- final store: out[l, h0..h0+7], 32B contiguous per thread ------------
#pragma unroll
    for (int rr = 0; rr < 8; rr++) {
        int l = rr * 256 + tid;            // = 16 j + dl; stage idx = l-linear
        const float* sp = stage + (size_t)((l >> 4) * 16 + (l & 15)) * 9;
        float4 v0 = make_float4(sp[0], sp[1], sp[2], sp[3]);
        float4 v1 = make_float4(sp[4], sp[5], sp[6], sp[7]);
        float* o = out + (size_t)l * FH + h0;
        *reinterpret_cast<float4*>(o)     = v0;
        *reinterpret_cast<float4*>(o + 4) = v1;
    }
}

// ---------------------------------------------------------------------------
// Generic fallback (correct for any shape; slow).
// ---------------------------------------------------------------------------
__global__ void k_generic(const float* __restrict__ log_dt,
                          const float* __restrict__ llnr,
                          const float* __restrict__ lim,
                          const float* __restrict__ W,
                          float* __restrict__ out,
                          int H, int N, int L)
{
    int idx = blockIdx.x * blockDim.x + threadIdx.x;
    if (idx >= L * H) return;
    int l = idx / H, h = idx - l * H;
    float dtr = expf(log_dt[2 * h + 0]);
    float dti = expf(log_dt[2 * h + 1]);
    float fl = (float)l;
    float sum = 0.0f;
    for (int n = 0; n < N; n++) {
        float lr = -expf(llnr[n]);
        float li = lim[n];
        float a = dtr * lr, b = dti * li;
        float ns = fmaxf(lr * lr + li * li, EPS2);
        float rr = lr / ns, ri = -li / ns;
        float ea = expf(a), sb, cb;
        sincosf(b, &sb, &cb);
        float edr = ea * cb - 1.0f, edi = ea * sb;
        float wr = W[(h * N + n) * 2 + 0], wi = W[(h * N + n) * 2 + 1];
        float tr = wr * edr - wi * edi, ti = wr * edi + wi * edr;
        float wkr = tr * rr - ti * ri, wki = tr * ri + ti * rr;
        float el = expf(a * fl), sl, cl;
        sincosf(b * fl, &sl, &cl);
        sum += wkr * (el * cl) - wki * (el * sl);
    }
    out[idx] = sum;
}

// ---------------------------------------------------------------------------
extern "C" void kernel_launch(void* const* d_in, const int* in_sizes, int n_in,
                              void* d_out, int out_size)
{
    const float* log_dt = (const float*)d_in[0];   // (H,2)
    const float* llnr   = (const float*)d_in[1];   // (N,)
    const float* lim    = (const float*)d_in[2];   // (N,)
    const float* W      = (const float*)d_in[3];   // (H,N,2)
    float* out = (float*)d_out;

    int H = in_sizes[0] / 2;
    int N = in_sizes[1];
    int L = out_size / H;

    if (H == FH && N == FN && L == FL) {
        cudaFuncSetAttribute(k_tc, cudaFuncAttributeMaxDynamicSharedMemorySize,
                             SMEM_TOTAL);
        k_tc<<<FH / 8, 256, SMEM_TOTAL>>>(log_dt, llnr, lim, W, out);
    } else {
        int tot = L * H;
        k_generic<<<(tot + 255) / 256, 256>>>(log_dt, llnr, lim, W, out, H, N, L);
    }
}

// round 15
// speedup vs baseline: 1.4112x; 1.0865x over previous
#include <cuda_runtime.h>
#include <cuda_bf16.h>
#include <cstdint>

// ---------------------------------------------------------------------------
// DSS kernel via warp-level tensor cores (mma.sync bf16, baseline sm_80+ PTX).
//
// out[l,h] = Re( sum_n Wk[h,n] * z_{h,n}^l ),  l = 32*j + dl  (j<64, dl<32).
//   A_h[j, k]  (M=64 x K=128) : k=2n -> Re(Wk z^32j), k=2n+1 -> Im(Wk z^32j)
//   B_h[dl, k] (N=32 x K=128) : k=2n -> Re(z^dl),     k=2n+1 -> -Im(z^dl)
//   D = A . B^T (fp32 accum)  => out[32j+dl, h].
// bf16 hi/lo split: D = Ah.Bh + Al.Bh + Ah.Bl.
// CTA = 4 h (sequential), 256 thr, 2 CTAs/SM; warp = (M-tile 0..3, N-half).
// ---------------------------------------------------------------------------

#define EPS2 1e-14f

#define FH 1024
#define FN 64
#define FL 2048

#define INV_2PI 0.15915494309189535f
#define PI2_HI  6.2831854820251465f
#define PI2_LO  (-1.7484556000744483e-7f)

// ---- smem layout (bytes). A/B rows padded to 264 bf16 = 528 B ----
#define APITCH     528
#define SMEM_A     0                       // 64 x 528 = 33792
#define SMEM_B     33792                   // 32 x 528 = 16896
#define SMEM_STAGE 50688                   // 2048 x 5 f32 = 40960
#define SMEM_CA    91648                   // float4[256] = 4096
#define SMEM_CG    95744                   // float2[256] = 2048
#define SMEM_TOTAL 97792

// ---- PTX helpers ----
__device__ __forceinline__ uint32_t smem_u32(const void* p) {
    uint32_t a;
    asm("{ .reg .u64 t; cvta.to.shared.u64 t, %1; cvt.u32.u64 %0, t; }"
        : "=r"(a) : "l"(p));
    return a;
}

#define LDMATRIX_X4(r0, r1, r2, r3, addr)                                    \
    asm volatile("ldmatrix.sync.aligned.m8n8.x4.shared.b16 {%0,%1,%2,%3}, [%4];" \
        : "=r"(r0), "=r"(r1), "=r"(r2), "=r"(r3) : "r"(addr))

#define MMA_BF16(d, a0, a1, a2, a3, b0, b1)                                  \
    asm volatile("mma.sync.aligned.m16n8k16.row.col.f32.bf16.bf16.f32 "      \
        "{%0,%1,%2,%3}, {%4,%5,%6,%7}, {%8,%9}, {%0,%1,%2,%3};"              \
        : "+f"((d)[0]), "+f"((d)[1]), "+f"((d)[2]), "+f"((d)[3])             \
        : "r"(a0), "r"(a1), "r"(a2), "r"(a3), "r"(b0), "r"(b1))

// packs r = {hi: bf16(y), lo: bf16(x)}  (memory order: x then y)
#define CVT2(r, x, y) asm("cvt.rn.satfinite.bf16x2.f32 %0, %1, %2;" : "=r"(r) : "f"(y), "f"(x))

// fast sin/cos with Cody-Waite reduction to [-pi, pi]
__device__ __forceinline__ void fast_sincos(float th, float* s, float* c)
{
    float k = rintf(th * INV_2PI);
    float r = fmaf(-k, PI2_HI, th);
    r = fmaf(-k, PI2_LO, r);
    *s = __sinf(r);
    *c = __cosf(r);
}
// same reduction, precise sincosf on the small residue
__device__ __forceinline__ void cw_sincos(float th, float* s, float* c)
{
    float k = rintf(th * INV_2PI);
    float r = fmaf(-k, PI2_HI, th);
    r = fmaf(-k, PI2_LO, r);
    sincosf(r, s, c);
}

// ---------------------------------------------------------------------------
__global__ void __launch_bounds__(256, 2) k_tc(
    const float* __restrict__ log_dt,
    const float* __restrict__ llnr,
    const float* __restrict__ lim,
    const float* __restrict__ W,
    float* __restrict__ out)
{
    extern __shared__ char smem[];
    const uint32_t sb = smem_u32(smem);
    const int tid  = threadIdx.x;
    const int wid  = tid >> 5;
    const int lane = tid & 31;
    const int h0   = blockIdx.x * 4;

    float4* cA = (float4*)(smem + SMEM_CA);   // (a, b, m16r, m16i)
    float2* cG = (float2*)(smem + SMEM_CG);   // (Wk_re, Wk_im)
    float*  stage = (float*)(smem + SMEM_STAGE);

    // ---- P1: per-(hh, n) constants, one per thread ---------------------------
    {
        int idx = tid;                      // 256 = 4 hh x 64 n
        int hh = idx >> 6, n = idx & 63;
        int h = h0 + hh;

        float lr = -expf(llnr[n]);
        float li = lim[n];
        float dtr = expf(log_dt[2 * h + 0]);
        float dti = expf(log_dt[2 * h + 1]);
        float a = dtr * lr;        // < 0
        float b = dti * li;

        // Wk = Wc * (exp(dtL)-1) * reciprocal_clamped(Lambda)
        float ns = fmaxf(lr * lr + li * li, EPS2);
        float rr =  lr / ns;
        float ri = -li / ns;
        float ea = expf(a), sbf, cbf;
        sincosf(b, &sbf, &cbf);
        float edr = ea * cbf - 1.0f;
        float edi = ea * sbf;
        float wr = W[(h * FN + n) * 2 + 0];
        float wi = W[(h * FN + n) * 2 + 1];
        float tr = wr * edr - wi * edi;
        float ti = wr * edi + wi * edr;
        float gr = tr * rr - ti * ri;
        float gi = tr * ri + ti * rr;

        // m16 = z^16 (CW-reduced angle, precise sincos)
        float s16, c16;
        cw_sincos(16.0f * b, &s16, &c16);
        float e16 = expf(16.0f * a);

        cA[idx] = make_float4(a, b, e16 * c16, e16 * s16);
        cG[idx] = make_float2(gr, gi);
    }
    __syncthreads();

    // warp roles: m-tile = wid & 3 (j rows 16m..), n-half = wid >> 2 (dl 16nh..)
    const int mtl = wid & 3;
    const int nhf = wid >> 2;

    const uint32_t a_lanebase = sb + SMEM_A
        + (uint32_t)(16 * mtl + (lane & 15)) * APITCH + ((lane >> 4) << 4);
    const uint32_t b_lanebase = sb + SMEM_B
        + (uint32_t)(16 * nhf + ((lane >> 4) & 1) * 8 + (lane & 7)) * APITCH
        + (((lane >> 3) & 1) << 4);

    const int n_ = tid & 63;
    const int q_ = tid >> 6;     // j-quarter 0..3 (16 j each)

    for (int hh = 0; hh < 4; hh++) {
        // ---- build A: S_j = Wk * z^(32 j); thread does j = 16 q_ .. +15 ------
        {
            float4 ab = cA[hh * 64 + n_];
            float2 G  = cG[hh * 64 + n_];
            float Sr = G.x, Si = G.y;
            if (q_) {            // rotate by z^(512 q_)
                float mult = 512.0f * (float)q_;
                float s, c;
                fast_sincos(ab.y * mult, &s, &c);
                float e = __expf(ab.x * mult);
                float zr = e * c, zi = e * s;
                float t = Sr * zr - Si * zi;
                Si = Sr * zi + Si * zr;
                Sr = t;
            }
            // m32 = m16^2
            const float mr = ab.z * ab.z - ab.w * ab.w;
            const float mi = 2.0f * ab.z * ab.w;
            uint32_t wbase = sb + SMEM_A + (uint32_t)(q_ * 16) * APITCH + 4u * n_;
#pragma unroll 8
            for (int s = 0; s < 16; s++) {
                uint32_t rh;
                CVT2(rh, Sr, Si);
                float frh = __uint_as_float(rh << 16);
                float fih = __uint_as_float(rh & 0xFFFF0000u);
                uint32_t rl;
                CVT2(rl, Sr - frh, Si - fih);
                asm volatile("st.shared.b32 [%0], %1;" :: "r"(wbase), "r"(rh) : "memory");
                asm volatile("st.shared.b32 [%0], %1;" :: "r"(wbase + 256u), "r"(rl) : "memory");
                wbase += APITCH;
                float t = Sr * mr - Si * mi;
                Si = Sr * mi + Si * mr;
                Sr = t;
            }
        }
        // ---- build B: (Re z^dl, -Im z^dl); threads 0..127 = (dh, n) ----------
        if (tid < 128) {
            const int dh = tid >> 6;        // dl-half 0/1
            float4 ab = cA[hh * 64 + n_];
            float e = __expf(ab.x);
            float s, c;
            fast_sincos(ab.y, &s, &c);
            float zr = e * c, zi = e * s;
            float Er, Ei;
            if (dh) { Er = ab.z;  Ei = ab.w; }   // z^16
            else    { Er = 1.0f;  Ei = 0.0f; }
            uint32_t wbase = sb + SMEM_B + (uint32_t)(dh * 16) * APITCH + 4u * n_;
#pragma unroll
            for (int dl = 0; dl < 16; dl++) {
                float vr = Er, vi = -Ei;
                uint32_t rh;
                CVT2(rh, vr, vi);
                float frh = __uint_as_float(rh << 16);
                float fih = __uint_as_float(rh & 0xFFFF0000u);
                uint32_t rl;
                CVT2(rl, vr - frh, vi - fih);
                asm volatile("st.shared.b32 [%0], %1;" :: "r"(wbase), "r"(rh) : "memory");
                asm volatile("st.shared.b32 [%0], %1;" :: "r"(wbase + 256u), "r"(rl) : "memory");
                wbase += APITCH;
                float t = Er * zr - Ei * zi;
                Ei = Er * zi + Ei * zr;
                Er = t;
            }
        }
        __syncthreads();

        // ---- MMA: 3 passes x 8 k-chunks x 2 N8-tiles -------------------------
        float d0[4] = {0.f, 0.f, 0.f, 0.f};
        float d1[4] = {0.f, 0.f, 0.f, 0.f};
#pragma unroll
        for (int pass = 0; pass < 3; pass++) {
            const uint32_t haB = (pass == 1) ? 256u : 0u;   // A lo half
            const uint32_t hbB = (pass == 2) ? 256u : 0u;   // B lo half
#pragma unroll
            for (int c = 0; c < 8; c++) {
                uint32_t a0, a1, a2, a3, b0, b1, b2, b3;
                LDMATRIX_X4(a0, a1, a2, a3, a_lanebase + haB + 32u * c);
                LDMATRIX_X4(b0, b1, b2, b3, b_lanebase + hbB + 32u * c);
                MMA_BF16(d0, a0, a1, a2, a3, b0, b1);   // dl 16nh + 0..7
                MMA_BF16(d1, a0, a1, a2, a3, b2, b3);   // dl 16nh + 8..15
            }
        }

        // ---- write D to stage[(32 j + dl)*5 + hh] ----------------------------
        {
            const int g  = lane >> 2;
            const int tc = lane & 3;
            const int j0 = 16 * mtl + g;
            const int j1 = j0 + 8;
            const int dA = 16 * nhf + 2 * tc;
            const int dB = dA + 8;
            stage[(j0 * 32 + dA)     * 5 + hh] = d0[0];
            stage[(j0 * 32 + dA + 1) * 5 + hh] = d0[1];
            stage[(j1 * 32 + dA)     * 5 + hh] = d0[2];
            stage[(j1 * 32 + dA + 1) * 5 + hh] = d0[3];
            stage[(j0 * 32 + dB)     * 5 + hh] = d1[0];
            stage[(j0 * 32 + dB + 1) * 5 + hh] = d1[1];
            stage[(j1 * 32 + dB)     * 5 + hh] = d1[2];
            stage[(j1 * 32 + dB + 1) * 5 + hh] = d1[3];
        }
        __syncthreads();   // all A/B reads done before next-h rebuild
    }

    // ---- final store: out[l, h0..h0+3] = float4, conflict-free stride-5 -----
#pragma unroll
    for (int rr = 0; rr < 8; rr++) {
        int l = rr * 256 + tid;           // l = 32 j + dl, stage is l-linear
        const float* sp = stage + (size_t)l * 5;
        float4 v = make_float4(sp[0], sp[1], sp[2], sp[3]);
        *reinterpret_cast<float4*>(out + (size_t)l * FH + h0) = v;
    }
}

// ---------------------------------------------------------------------------
// Generic fallback (correct for any shape; slow).
// ---------------------------------------------------------------------------
__global__ void k_generic(const float* __restrict__ log_dt,
                          const float* __restrict__ llnr,
                          const float* __restrict__ lim,
                          const float* __restrict__ W,
                          float* __restrict__ out,
                          int H, int N, int L)
{
    int idx = blockIdx.x * blockDim.x + threadIdx.x;
    if (idx >= L * H) return;
    int l = idx / H, h = idx - l * H;
    float dtr = expf(log_dt[2 * h + 0]);
    float dti = expf(log_dt[2 * h + 1]);
    float fl = (float)l;
    float sum = 0.0f;
    for (int n = 0; n < N; n++) {
        float lr = -expf(llnr[n]);
        float li = lim[n];
        float a = dtr * lr, b = dti * li;
        float ns = fmaxf(lr * lr + li * li, EPS2);
        float rr = lr / ns, ri = -li / ns;
        float ea = expf(a), sb, cb;
        sincosf(b, &sb, &cb);
        float edr = ea * cb - 1.0f, edi = ea * sb;
        float wr = W[(h * N + n) * 2 + 0], wi = W[(h * N + n) * 2 + 1];
        float tr = wr * edr - wi * edi, ti = wr * edi + wi * edr;
        float wkr = tr * rr - ti * ri, wki = tr * ri + ti * rr;
        float el = expf(a * fl), sl, cl;
        sincosf(b * fl, &sl, &cl);
        sum += wkr * (el * cl) - wki * (el * sl);
    }
    out[idx] = sum;
}

// ---------------------------------------------------------------------------
extern "C" void kernel_launch(void* const* d_in, const int* in_sizes, int n_in,
                              void* d_out, int out_size)
{
    const float* log_dt = (const float*)d_in[0];   // (H,2)
    const float* llnr   = (const float*)d_in[1];   // (N,)
    const float* lim    = (const float*)d_in[2];   // (N,)
    const float* W      = (const float*)d_in[3];   // (H,N,2)
    float* out = (float*)d_out;

    int H = in_sizes[0] / 2;
    int N = in_sizes[1];
    int L = out_size / H;

    if (H == FH && N == FN && L == FL) {
        cudaFuncSetAttribute(k_tc, cudaFuncAttributeMaxDynamicSharedMemorySize,
                             SMEM_TOTAL);
        k_tc<<<FH / 4, 256, SMEM_TOTAL>>>(log_dt, llnr, lim, W, out);
    } else {
        int tot = L * H;
        k_generic<<<(tot + 255) / 256, 256>>>(log_dt, llnr, lim, W, out, H, N, L);
    }
}

// round 16
// speedup vs baseline: 1.4509x; 1.0281x over previous
#include <cuda_runtime.h>
#include <cuda_bf16.h>
#include <cstdint>

// ---------------------------------------------------------------------------
// DSS kernel via warp-level tensor cores (mma.sync bf16, baseline sm_80+ PTX).
//
// out[l,h] = Re( sum_n Wk[h,n] * z_{h,n}^l ),  l = 32*j + dl  (j<64, dl<32).
//   A_h[j, k]  (M=64 x K=128) : k=2n -> Re(Wk z^32j), k=2n+1 -> Im(Wk z^32j)
//   B_h[dl, k] (N=32 x K=128) : k=2n -> Re(z^dl),     k=2n+1 -> -Im(z^dl)
//   D = A . B^T (fp32 accum)  => out[32j+dl, h].
// bf16 hi/lo split: D = Ah.Bh + Al.Bh + Ah.Bl.
// CTA = 4 h (sequential), 256 thr, 2 CTAs/SM; warp = (M-tile 0..3, N-half).
// Chunk-major MMA loop: each fragment loaded ONCE (4 ldmatrix.x4 / chunk,
// 6 MMAs / chunk) — 32 ldmatrix vs 48 in the pass-major version.
// ---------------------------------------------------------------------------

#define EPS2 1e-14f

#define FH 1024
#define FN 64
#define FL 2048

#define INV_2PI 0.15915494309189535f
#define PI2_HI  6.2831854820251465f
#define PI2_LO  (-1.7484556000744483e-7f)

// ---- smem layout (bytes). A/B rows padded to 264 bf16 = 528 B ----
#define APITCH     528
#define SMEM_A     0                       // 64 x 528 = 33792
#define SMEM_B     33792                   // 32 x 528 = 16896
#define SMEM_STAGE 50688                   // 2048 x 5 f32 = 40960
#define SMEM_CA    91648                   // float4[256] = 4096
#define SMEM_CG    95744                   // float2[256] = 2048
#define SMEM_TOTAL 97792

// ---- PTX helpers ----
__device__ __forceinline__ uint32_t smem_u32(const void* p) {
    uint32_t a;
    asm("{ .reg .u64 t; cvta.to.shared.u64 t, %1; cvt.u32.u64 %0, t; }"
        : "=r"(a) : "l"(p));
    return a;
}

#define LDMATRIX_X4(r0, r1, r2, r3, addr)                                    \
    asm volatile("ldmatrix.sync.aligned.m8n8.x4.shared.b16 {%0,%1,%2,%3}, [%4];" \
        : "=r"(r0), "=r"(r1), "=r"(r2), "=r"(r3) : "r"(addr))

#define MMA_BF16(d, a0, a1, a2, a3, b0, b1)                                  \
    asm volatile("mma.sync.aligned.m16n8k16.row.col.f32.bf16.bf16.f32 "      \
        "{%0,%1,%2,%3}, {%4,%5,%6,%7}, {%8,%9}, {%0,%1,%2,%3};"              \
        : "+f"((d)[0]), "+f"((d)[1]), "+f"((d)[2]), "+f"((d)[3])             \
        : "r"(a0), "r"(a1), "r"(a2), "r"(a3), "r"(b0), "r"(b1))

// packs r = {hi: bf16(y), lo: bf16(x)}  (memory order: x then y)
#define CVT2(r, x, y) asm("cvt.rn.satfinite.bf16x2.f32 %0, %1, %2;" : "=r"(r) : "f"(y), "f"(x))

// fast sin/cos with Cody-Waite reduction to [-pi, pi]
__device__ __forceinline__ void fast_sincos(float th, float* s, float* c)
{
    float k = rintf(th * INV_2PI);
    float r = fmaf(-k, PI2_HI, th);
    r = fmaf(-k, PI2_LO, r);
    *s = __sinf(r);
    *c = __cosf(r);
}
// same reduction, precise sincosf on the small residue
__device__ __forceinline__ void cw_sincos(float th, float* s, float* c)
{
    float k = rintf(th * INV_2PI);
    float r = fmaf(-k, PI2_HI, th);
    r = fmaf(-k, PI2_LO, r);
    sincosf(r, s, c);
}

// ---------------------------------------------------------------------------
__global__ void __launch_bounds__(256, 2) k_tc(
    const float* __restrict__ log_dt,
    const float* __restrict__ llnr,
    const float* __restrict__ lim,
    const float* __restrict__ W,
    float* __restrict__ out)
{
    extern __shared__ char smem[];
    const uint32_t sb = smem_u32(smem);
    const int tid  = threadIdx.x;
    const int wid  = tid >> 5;
    const int lane = tid & 31;
    const int h0   = blockIdx.x * 4;

    float4* cA = (float4*)(smem + SMEM_CA);   // (a, b, m16r, m16i)
    float2* cG = (float2*)(smem + SMEM_CG);   // (Wk_re, Wk_im)
    float*  stage = (float*)(smem + SMEM_STAGE);

    // ---- P1: per-(hh, n) constants, one per thread ---------------------------
    {
        int idx = tid;                      // 256 = 4 hh x 64 n
        int hh = idx >> 6, n = idx & 63;
        int h = h0 + hh;

        float lr = -expf(llnr[n]);
        float li = lim[n];
        float dtr = expf(log_dt[2 * h + 0]);
        float dti = expf(log_dt[2 * h + 1]);
        float a = dtr * lr;        // < 0
        float b = dti * li;

        // Wk = Wc * (exp(dtL)-1) * reciprocal_clamped(Lambda)
        float ns = fmaxf(lr * lr + li * li, EPS2);
        float rr =  lr / ns;
        float ri = -li / ns;
        float ea = expf(a), sbf, cbf;
        sincosf(b, &sbf, &cbf);
        float edr = ea * cbf - 1.0f;
        float edi = ea * sbf;
        float wr = W[(h * FN + n) * 2 + 0];
        float wi = W[(h * FN + n) * 2 + 1];
        float tr = wr * edr - wi * edi;
        float ti = wr * edi + wi * edr;
        float gr = tr * rr - ti * ri;
        float gi = tr * ri + ti * rr;

        // m16 = z^16 (CW-reduced angle, precise sincos)
        float s16, c16;
        cw_sincos(16.0f * b, &s16, &c16);
        float e16 = expf(16.0f * a);

        cA[idx] = make_float4(a, b, e16 * c16, e16 * s16);
        cG[idx] = make_float2(gr, gi);
    }
    __syncthreads();

    // warp roles: m-tile = wid & 3 (j rows 16m..), n-half = wid >> 2 (dl 16nh..)
    const int mtl = wid & 3;
    const int nhf = wid >> 2;

    const uint32_t a_lanebase = sb + SMEM_A
        + (uint32_t)(16 * mtl + (lane & 15)) * APITCH + ((lane >> 4) << 4);
    const uint32_t b_lanebase = sb + SMEM_B
        + (uint32_t)(16 * nhf + ((lane >> 4) & 1) * 8 + (lane & 7)) * APITCH
        + (((lane >> 3) & 1) << 4);

    const int n_ = tid & 63;
    const int q_ = tid >> 6;     // j-quarter 0..3 (16 j each)

    for (int hh = 0; hh < 4; hh++) {
        // ---- build A: S_j = Wk * z^(32 j); thread does j = 16 q_ .. +15 ------
        {
            float4 ab = cA[hh * 64 + n_];
            float2 G  = cG[hh * 64 + n_];
            float Sr = G.x, Si = G.y;
            if (q_) {            // rotate by z^(512 q_)
                float mult = 512.0f * (float)q_;
                float s, c;
                fast_sincos(ab.y * mult, &s, &c);
                float e = __expf(ab.x * mult);
                float zr = e * c, zi = e * s;
                float t = Sr * zr - Si * zi;
                Si = Sr * zi + Si * zr;
                Sr = t;
            }
            // m32 = m16^2
            const float mr = ab.z * ab.z - ab.w * ab.w;
            const float mi = 2.0f * ab.z * ab.w;
            uint32_t wbase = sb + SMEM_A + (uint32_t)(q_ * 16) * APITCH + 4u * n_;
#pragma unroll 8
            for (int s = 0; s < 16; s++) {
                uint32_t rh;
                CVT2(rh, Sr, Si);
                float frh = __uint_as_float(rh << 16);
                float fih = __uint_as_float(rh & 0xFFFF0000u);
                uint32_t rl;
                CVT2(rl, Sr - frh, Si - fih);
                asm volatile("st.shared.b32 [%0], %1;" :: "r"(wbase), "r"(rh) : "memory");
                asm volatile("st.shared.b32 [%0], %1;" :: "r"(wbase + 256u), "r"(rl) : "memory");
                wbase += APITCH;
                float t = Sr * mr - Si * mi;
                Si = Sr * mi + Si * mr;
                Sr = t;
            }
        }
        // ---- build B: (Re z^dl, -Im z^dl); threads 0..127 = (dh, n) ----------
        if (tid < 128) {
            const int dh = tid >> 6;        // dl-half 0/1
            float4 ab = cA[hh * 64 + n_];
            float e = __expf(ab.x);
            float s, c;
            fast_sincos(ab.y, &s, &c);
            float zr = e * c, zi = e * s;
            float Er, Ei;
            if (dh) { Er = ab.z;  Ei = ab.w; }   // z^16
            else    { Er = 1.0f;  Ei = 0.0f; }
            uint32_t wbase = sb + SMEM_B + (uint32_t)(dh * 16) * APITCH + 4u * n_;
#pragma unroll
            for (int dl = 0; dl < 16; dl++) {
                float vr = Er, vi = -Ei;
                uint32_t rh;
                CVT2(rh, vr, vi);
                float frh = __uint_as_float(rh << 16);
                float fih = __uint_as_float(rh & 0xFFFF0000u);
                uint32_t rl;
                CVT2(rl, vr - frh, vi - fih);
                asm volatile("st.shared.b32 [%0], %1;" :: "r"(wbase), "r"(rh) : "memory");
                asm volatile("st.shared.b32 [%0], %1;" :: "r"(wbase + 256u), "r"(rl) : "memory");
                wbase += APITCH;
                float t = Er * zr - Ei * zi;
                Ei = Er * zi + Ei * zr;
                Er = t;
            }
        }
        __syncthreads();

        // ---- MMA: chunk-major; 4 ldmatrix.x4 + 6 MMAs per k-chunk ------------
        float d0[4] = {0.f, 0.f, 0.f, 0.f};
        float d1[4] = {0.f, 0.f, 0.f, 0.f};
#pragma unroll
        for (int c = 0; c < 8; c++) {
            uint32_t ah0, ah1, ah2, ah3, al0, al1, al2, al3;
            uint32_t bh0, bh1, bh2, bh3, bl0, bl1, bl2, bl3;
            LDMATRIX_X4(ah0, ah1, ah2, ah3, a_lanebase + 32u * c);          // A hi
            LDMATRIX_X4(al0, al1, al2, al3, a_lanebase + 256u + 32u * c);   // A lo
            LDMATRIX_X4(bh0, bh1, bh2, bh3, b_lanebase + 32u * c);          // B hi
            LDMATRIX_X4(bl0, bl1, bl2, bl3, b_lanebase + 256u + 32u * c);   // B lo
            MMA_BF16(d0, ah0, ah1, ah2, ah3, bh0, bh1);
            MMA_BF16(d1, ah0, ah1, ah2, ah3, bh2, bh3);
            MMA_BF16(d0, al0, al1, al2, al3, bh0, bh1);
            MMA_BF16(d1, al0, al1, al2, al3, bh2, bh3);
            MMA_BF16(d0, ah0, ah1, ah2, ah3, bl0, bl1);
            MMA_BF16(d1, ah0, ah1, ah2, ah3, bl2, bl3);
        }

        // ---- write D to stage[(32 j + dl)*5 + hh] ----------------------------
        {
            const int g  = lane >> 2;
            const int tc = lane & 3;
            const int j0 = 16 * mtl + g;
            const int j1 = j0 + 8;
            const int dA = 16 * nhf + 2 * tc;
            const int dB = dA + 8;
            stage[(j0 * 32 + dA)     * 5 + hh] = d0[0];
            stage[(j0 * 32 + dA + 1) * 5 + hh] = d0[1];
            stage[(j1 * 32 + dA)     * 5 + hh] = d0[2];
            stage[(j1 * 32 + dA + 1) * 5 + hh] = d0[3];
            stage[(j0 * 32 + dB)     * 5 + hh] = d1[0];
            stage[(j0 * 32 + dB + 1) * 5 + hh] = d1[1];
            stage[(j1 * 32 + dB)     * 5 + hh] = d1[2];
            stage[(j1 * 32 + dB + 1) * 5 + hh] = d1[3];
        }
        __syncthreads();   // all A/B reads done before next-h rebuild
    }

    // ---- final store: out[l, h0..h0+3] = float4, conflict-free stride-5 -----
#pragma unroll
    for (int rr = 0; rr < 8; rr++) {
        int l = rr * 256 + tid;           // l = 32 j + dl, stage is l-linear
        const float* sp = stage + (size_t)l * 5;
        float4 v = make_float4(sp[0], sp[1], sp[2], sp[3]);
        *reinterpret_cast<float4*>(out + (size_t)l * FH + h0) = v;
    }
}

// ---------------------------------------------------------------------------
// Generic fallback (correct for any shape; slow).
// ---------------------------------------------------------------------------
__global__ void k_generic(const float* __restrict__ log_dt,
                          const float* __restrict__ llnr,
                          const float* __restrict__ lim,
                          const float* __restrict__ W,
                          float* __restrict__ out,
                          int H, int N, int L)
{
    int idx = blockIdx.x * blockDim.x + threadIdx.x;
    if (idx >= L * H) return;
    int l = idx / H, h = idx - l * H;
    float dtr = expf(log_dt[2 * h + 0]);
    float dti = expf(log_dt[2 * h + 1]);
    float fl = (float)l;
    float sum = 0.0f;
    for (int n = 0; n < N; n++) {
        float lr = -expf(llnr[n]);
        float li = lim[n];
        float a = dtr * lr, b = dti * li;
        float ns = fmaxf(lr * lr + li * li, EPS2);
        float rr = lr / ns, ri = -li / ns;
        float ea = expf(a), sb, cb;
        sincosf(b, &sb, &cb);
        float edr = ea * cb - 1.0f, edi = ea * sb;
        float wr = W[(h * N + n) * 2 + 0], wi = W[(h * N + n) * 2 + 1];
        float tr = wr * edr - wi * edi, ti = wr * edi + wi * edr;
        float wkr = tr * rr - ti * ri, wki = tr * ri + ti * rr;
        float el = expf(a * fl), sl, cl;
        sincosf(b * fl, &sl, &cl);
        sum += wkr * (el * cl) - wki * (el * sl);
    }
    out[idx] = sum;
}

// ---------------------------------------------------------------------------
extern "C" void kernel_launch(void* const* d_in, const int* in_sizes, int n_in,
                              void* d_out, int out_size)
{
    const float* log_dt = (const float*)d_in[0];   // (H,2)
    const float* llnr   = (const float*)d_in[1];   // (N,)
    const float* lim    = (const float*)d_in[2];   // (N,)
    const float* W      = (const float*)d_in[3];   // (H,N,2)
    float* out = (float*)d_out;

    int H = in_sizes[0] / 2;
    int N = in_sizes[1];
    int L = out_size / H;

    if (H == FH && N == FN && L == FL) {
        cudaFuncSetAttribute(k_tc, cudaFuncAttributeMaxDynamicSharedMemorySize,
                             SMEM_TOTAL);
        k_tc<<<FH / 4, 256, SMEM_TOTAL>>>(log_dt, llnr, lim, W, out);
    } else {
        int tot = L * H;
        k_generic<<<(tot + 255) / 256, 256>>>(log_dt, llnr, lim, W, out, H, N, L);
    }
}